// round 1
// baseline (speedup 1.0000x reference)
#include <cuda_runtime.h>

static constexpr int IMG   = 128;
static constexpr int NPIX  = IMG * IMG;      // 16384
static constexpr int CH    = 64;
static constexpr int NHEAD = 8;
static constexpr int HIDN  = 128;
static constexpr float LNEPS  = 1e-5f;
static constexpr float QSCALE = 0.35355339059327373f;   // 8^-0.5

// ---------------- scratch (no allocations allowed) ----------------
__device__ __align__(16) float g_q[NHEAD * NPIX * 8];
__device__ __align__(16) float g_k[NHEAD * NPIX * 8];
__device__ __align__(16) float g_v[NHEAD * NPIX * 8];
__device__ float g_att[CH * NPIX];
__device__ float g_x1 [CH * NPIX];
__device__ float g_y  [CH * NPIX];
__device__ float g_h1 [HIDN * NPIX];

// =================================================================
// Kernel A: LN1 -> QKV (192x64 GEMV per pixel) -> qLN, kLN -> store
// q/k/v in head-major layout [head][pixel][8]
// =================================================================
static constexpr int SMEM_A = (64 * 192 + 64 * 128) * 4;   // 81920 B

__global__ void __launch_bounds__(128)
kA(const float* __restrict__ x, const float* __restrict__ n1w, const float* __restrict__ n1b,
   const float* __restrict__ qkvw, const float* __restrict__ qkvb,
   const float* __restrict__ qnw, const float* __restrict__ qnb,
   const float* __restrict__ knw, const float* __restrict__ knb)
{
    extern __shared__ float smA[];
    float* wt = smA;              // transposed weights: wt[c*192 + o]
    float* xs = smA + 64 * 192;   // normalized input:   xs[c*128 + tid]
    const int tid = threadIdx.x;

    for (int i = tid; i < 192 * 64; i += 128) {
        int o = i >> 6, c = i & 63;
        wt[c * 192 + o] = qkvw[i];
    }

    const int p = blockIdx.x * 128 + tid;
    float mean = 0.f;
    for (int c = 0; c < CH; c++) {
        float v = x[c * NPIX + p];
        xs[c * 128 + tid] = v;
        mean += v;
    }
    mean *= (1.0f / CH);
    float var = 0.f;
    for (int c = 0; c < CH; c++) { float d = xs[c * 128 + tid] - mean; var += d * d; }
    float inv = rsqrtf(var * (1.0f / CH) + LNEPS);
    for (int c = 0; c < CH; c++) {
        float v = xs[c * 128 + tid];
        xs[c * 128 + tid] = (v - mean) * inv * n1w[c] + n1b[c];
    }
    __syncthreads();

    float acc[64];

    // ---------------- Q ----------------
    #pragma unroll
    for (int o = 0; o < 64; o++) acc[o] = 0.f;
    for (int c = 0; c < 64; c++) {
        float xc = xs[c * 128 + tid];
        const float* wr = wt + c * 192;
        #pragma unroll
        for (int o = 0; o < 64; o++) acc[o] += wr[o] * xc;
    }
    {
        float m2 = 0.f;
        #pragma unroll
        for (int o = 0; o < 64; o++) { acc[o] += qkvb[o]; m2 += acc[o]; }
        m2 *= (1.f / 64);
        float v2 = 0.f;
        #pragma unroll
        for (int o = 0; o < 64; o++) { float d = acc[o] - m2; v2 += d * d; }
        float iv = rsqrtf(v2 * (1.f / 64) + LNEPS);
        #pragma unroll
        for (int o = 0; o < 64; o++) acc[o] = ((acc[o] - m2) * iv * qnw[o] + qnb[o]) * QSCALE;
        #pragma unroll
        for (int h = 0; h < 8; h++) {
            float4* dst = reinterpret_cast<float4*>(&g_q[(h * NPIX + p) * 8]);
            dst[0] = make_float4(acc[h*8+0], acc[h*8+1], acc[h*8+2], acc[h*8+3]);
            dst[1] = make_float4(acc[h*8+4], acc[h*8+5], acc[h*8+6], acc[h*8+7]);
        }
    }

    // ---------------- K ----------------
    #pragma unroll
    for (int o = 0; o < 64; o++) acc[o] = 0.f;
    for (int c = 0; c < 64; c++) {
        float xc = xs[c * 128 + tid];
        const float* wr = wt + c * 192 + 64;
        #pragma unroll
        for (int o = 0; o < 64; o++) acc[o] += wr[o] * xc;
    }
    {
        float m2 = 0.f;
        #pragma unroll
        for (int o = 0; o < 64; o++) { acc[o] += qkvb[64 + o]; m2 += acc[o]; }
        m2 *= (1.f / 64);
        float v2 = 0.f;
        #pragma unroll
        for (int o = 0; o < 64; o++) { float d = acc[o] - m2; v2 += d * d; }
        float iv = rsqrtf(v2 * (1.f / 64) + LNEPS);
        #pragma unroll
        for (int o = 0; o < 64; o++) acc[o] = (acc[o] - m2) * iv * knw[o] + knb[o];
        #pragma unroll
        for (int h = 0; h < 8; h++) {
            float4* dst = reinterpret_cast<float4*>(&g_k[(h * NPIX + p) * 8]);
            dst[0] = make_float4(acc[h*8+0], acc[h*8+1], acc[h*8+2], acc[h*8+3]);
            dst[1] = make_float4(acc[h*8+4], acc[h*8+5], acc[h*8+6], acc[h*8+7]);
        }
    }

    // ---------------- V ----------------
    #pragma unroll
    for (int o = 0; o < 64; o++) acc[o] = 0.f;
    for (int c = 0; c < 64; c++) {
        float xc = xs[c * 128 + tid];
        const float* wr = wt + c * 192 + 128;
        #pragma unroll
        for (int o = 0; o < 64; o++) acc[o] += wr[o] * xc;
    }
    {
        #pragma unroll
        for (int o = 0; o < 64; o++) acc[o] += qkvb[128 + o];
        #pragma unroll
        for (int h = 0; h < 8; h++) {
            float4* dst = reinterpret_cast<float4*>(&g_v[(h * NPIX + p) * 8]);
            dst[0] = make_float4(acc[h*8+0], acc[h*8+1], acc[h*8+2], acc[h*8+3]);
            dst[1] = make_float4(acc[h*8+4], acc[h*8+5], acc[h*8+6], acc[h*8+7]);
        }
    }
}

// =================================================================
// Kernel B: neighborhood attention. Block = (16x16 pixel tile, head).
// Halo 44x44 of K and V (one head) staged in smem as 4 float2-planes
// each (conflict-free LDS.64). One-pass online softmax per thread.
// =================================================================
static constexpr int PLANE  = 44 * 45;          // float2 elements per plane (row stride 45)
static constexpr int SMEM_B = 8 * PLANE * 8;    // 126720 B

__global__ void __launch_bounds__(256)
kB()
{
    extern __shared__ float2 sm[];   // planes 0..3 = K d-pairs, 4..7 = V d-pairs
    const int tile = blockIdx.x, head = blockIdx.y;
    const int th0 = (tile >> 3) << 4, tw0 = (tile & 7) << 4;
    const int tid = threadIdx.x;
    const float* kg = g_k + head * (NPIX * 8);
    const float* vg = g_v + head * (NPIX * 8);

    // fill halo: 44 rows x 44 cols x 8 floats, K and V
    for (int e = tid; e < 2 * 44 * 88; e += 256) {
        int arr = (e >= 44 * 88) ? 1 : 0;
        int i = e - arr * (44 * 88);
        int r = i / 88, j = i - r * 88;
        int hh = min(max(th0 - 16 + r, 0), 127);
        int col = j >> 1;
        int ww = min(max(tw0 - 16 + col, 0), 127);
        const float* src = arr ? vg : kg;
        float4 val = *reinterpret_cast<const float4*>(src + (hh * 128 + ww) * 8 + (j & 1) * 4);
        float2* dst = sm + (arr * 4 + (j & 1) * 2) * PLANE + r * 45 + col;
        dst[0]     = make_float2(val.x, val.y);
        dst[PLANE] = make_float2(val.z, val.w);
    }
    __syncthreads();

    const int qy = tid >> 4, qx = tid & 15;
    const int h = th0 + qy, w = tw0 + qx;
    const int p = h * 128 + w;

    float q[8];
    *reinterpret_cast<float4*>(q)     = *reinterpret_cast<const float4*>(&g_q[(head * NPIX + p) * 8]);
    *reinterpret_cast<float4*>(q + 4) = *reinterpret_cast<const float4*>(&g_q[(head * NPIX + p) * 8 + 4]);

    float m = -1e30f, l = 0.f;
    float acc[8];
    #pragma unroll
    for (int d = 0; d < 8; d++) acc[d] = 0.f;

    for (int a = 0; a < 8; a++) {
        int oh = 4 * a - 16;
        bool vh = (unsigned)(h + oh) < 128u;
        int rbase = (qy + 16 + oh) * 45;
        #pragma unroll
        for (int b = 0; b < 8; b++) {
            int ow = 4 * b - 16;
            bool ok = vh && ((unsigned)(w + ow) < 128u);
            int off = rbase + qx + 16 + ow;
            float2 k0 = sm[off], k1 = sm[PLANE + off], k2 = sm[2 * PLANE + off], k3 = sm[3 * PLANE + off];
            float s = q[0]*k0.x + q[1]*k0.y + q[2]*k1.x + q[3]*k1.y
                    + q[4]*k2.x + q[5]*k2.y + q[6]*k3.x + q[7]*k3.y;
            s = ok ? s : -1e30f;
            float mn   = fmaxf(m, s);
            float corr = __expf(m - mn);
            float e    = __expf(s - mn);
            l = l * corr + e;
            float2 v0 = sm[4*PLANE + off], v1 = sm[5*PLANE + off], v2 = sm[6*PLANE + off], v3 = sm[7*PLANE + off];
            acc[0] = acc[0] * corr + e * v0.x;
            acc[1] = acc[1] * corr + e * v0.y;
            acc[2] = acc[2] * corr + e * v1.x;
            acc[3] = acc[3] * corr + e * v1.y;
            acc[4] = acc[4] * corr + e * v2.x;
            acc[5] = acc[5] * corr + e * v2.y;
            acc[6] = acc[6] * corr + e * v3.x;
            acc[7] = acc[7] * corr + e * v3.y;
            m = mn;
        }
    }
    float rl = 1.0f / l;
    #pragma unroll
    for (int d = 0; d < 8; d++)
        g_att[(head * 8 + d) * NPIX + p] = acc[d] * rl;
}

// =================================================================
// Kernel C: proj (64x64) + gamma1*o + residual -> x1; LN2 -> y
// =================================================================
__global__ void __launch_bounds__(128)
kC(const float* __restrict__ x, const float* __restrict__ projw, const float* __restrict__ projb,
   const float* __restrict__ g1, const float* __restrict__ n2w, const float* __restrict__ n2b)
{
    __shared__ float wt[64 * 64];
    const int tid = threadIdx.x;
    for (int i = tid; i < 64 * 64; i += 128) { int o = i >> 6, c = i & 63; wt[c * 64 + o] = projw[i]; }
    __syncthreads();
    const int p = blockIdx.x * 128 + tid;
    float acc[64];
    #pragma unroll
    for (int o = 0; o < 64; o++) acc[o] = 0.f;
    #pragma unroll 4
    for (int c = 0; c < 64; c++) {
        float a = g_att[c * NPIX + p];
        const float* wr = wt + c * 64;
        #pragma unroll
        for (int o = 0; o < 64; o++) acc[o] += wr[o] * a;
    }
    float mean = 0.f;
    #pragma unroll
    for (int o = 0; o < 64; o++) {
        float xv = x[o * NPIX + p] + g1[o] * (acc[o] + projb[o]);
        g_x1[o * NPIX + p] = xv;
        acc[o] = xv;
        mean += xv;
    }
    mean *= (1.f / 64);
    float var = 0.f;
    #pragma unroll
    for (int o = 0; o < 64; o++) { float d = acc[o] - mean; var += d * d; }
    float inv = rsqrtf(var * (1.f / 64) + LNEPS);
    #pragma unroll
    for (int o = 0; o < 64; o++)
        g_y[o * NPIX + p] = (acc[o] - mean) * inv * n2w[o] + n2b[o];
}

// =================================================================
// Kernel D: fc1 (128x64) + LN + SiLU -> h1
// =================================================================
__global__ void __launch_bounds__(128)
kD(const float* __restrict__ fc1w, const float* __restrict__ fc1b,
   const float* __restrict__ mnw, const float* __restrict__ mnb)
{
    __shared__ float wt[64 * 128];      // wt[c*128 + o]
    const int tid = threadIdx.x;
    for (int i = tid; i < 128 * 64; i += 128) { int o = i >> 6, c = i & 63; wt[c * 128 + o] = fc1w[i]; }
    __syncthreads();
    const int p = blockIdx.x * 128 + tid;
    float acc[128];
    #pragma unroll
    for (int o = 0; o < 128; o++) acc[o] = 0.f;
    #pragma unroll 4
    for (int c = 0; c < 64; c++) {
        float yv = g_y[c * NPIX + p];
        const float* wr = wt + c * 128;
        #pragma unroll
        for (int o = 0; o < 128; o++) acc[o] += wr[o] * yv;
    }
    float mean = 0.f;
    #pragma unroll
    for (int o = 0; o < 128; o++) { acc[o] += fc1b[o]; mean += acc[o]; }
    mean *= (1.f / 128);
    float var = 0.f;
    #pragma unroll
    for (int o = 0; o < 128; o++) { float d = acc[o] - mean; var += d * d; }
    float inv = rsqrtf(var * (1.f / 128) + LNEPS);
    #pragma unroll
    for (int o = 0; o < 128; o++) {
        float hh = (acc[o] - mean) * inv * mnw[o] + mnb[o];
        g_h1[o * NPIX + p] = hh / (1.f + __expf(-hh));
    }
}

// =================================================================
// Kernel E: fc2 (64x128) + gamma2 + residual -> out
// =================================================================
__global__ void __launch_bounds__(128)
kE(const float* __restrict__ fc2w, const float* __restrict__ fc2b,
   const float* __restrict__ g2, float* __restrict__ out)
{
    __shared__ float wt[128 * 64];      // wt[c*64 + o]
    const int tid = threadIdx.x;
    for (int i = tid; i < 64 * 128; i += 128) { int o = i >> 7, c = i & 127; wt[c * 64 + o] = fc2w[i]; }
    __syncthreads();
    const int p = blockIdx.x * 128 + tid;
    float acc[64];
    #pragma unroll
    for (int o = 0; o < 64; o++) acc[o] = 0.f;
    #pragma unroll 4
    for (int c = 0; c < 128; c++) {
        float hv = g_h1[c * NPIX + p];
        const float* wr = wt + c * 64;
        #pragma unroll
        for (int o = 0; o < 64; o++) acc[o] += wr[o] * hv;
    }
    #pragma unroll
    for (int o = 0; o < 64; o++)
        out[o * NPIX + p] = g_x1[o * NPIX + p] + g2[o] * (acc[o] + fc2b[o]);
}

// =================================================================
extern "C" void kernel_launch(void* const* d_in, const int* in_sizes, int n_in,
                              void* d_out, int out_size)
{
    const float* x     = (const float*)d_in[0];
    const float* n1w   = (const float*)d_in[1];
    const float* n1b   = (const float*)d_in[2];
    const float* qkvw  = (const float*)d_in[3];
    const float* qkvb  = (const float*)d_in[4];
    const float* qnw   = (const float*)d_in[5];
    const float* qnb   = (const float*)d_in[6];
    const float* knw   = (const float*)d_in[7];
    const float* knb   = (const float*)d_in[8];
    const float* projw = (const float*)d_in[9];
    const float* projb = (const float*)d_in[10];
    const float* g1    = (const float*)d_in[11];
    const float* n2w   = (const float*)d_in[12];
    const float* n2b   = (const float*)d_in[13];
    const float* fc1w  = (const float*)d_in[14];
    const float* fc1b  = (const float*)d_in[15];
    const float* mnw   = (const float*)d_in[16];
    const float* mnb   = (const float*)d_in[17];
    const float* fc2w  = (const float*)d_in[18];
    const float* fc2b  = (const float*)d_in[19];
    const float* g2    = (const float*)d_in[20];
    float* out = (float*)d_out;

    cudaFuncSetAttribute(kA, cudaFuncAttributeMaxDynamicSharedMemorySize, SMEM_A);
    cudaFuncSetAttribute(kB, cudaFuncAttributeMaxDynamicSharedMemorySize, SMEM_B);

    kA<<<128, 128, SMEM_A>>>(x, n1w, n1b, qkvw, qkvb, qnw, qnb, knw, knb);
    kB<<<dim3(64, 8), 256, SMEM_B>>>();
    kC<<<128, 128>>>(x, projw, projb, g1, n2w, n2b);
    kD<<<128, 128>>>(fc1w, fc1b, mnw, mnb);
    kE<<<128, 128>>>(fc2w, fc2b, g2, out);
}